// round 8
// baseline (speedup 1.0000x reference)
#include <cuda_runtime.h>
#include <cuda_fp16.h>

// Trilinear interpolation: fp16 channel-last scratch + 2-lane 256-bit gather,
// occupancy-capped regs + packed f32x2 FMA accumulation.
//   input  d_in[0]: float32 [16, 128, 128, 128]  (C, z, y, x)
//   coords d_in[1]: float32 [1000000, 3] in [-1, 1]
//   out    d_out  : float32 [16, 1000000]

#define GS        128
#define NCH       16
#define NSPATIAL  (GS * GS * GS)
#define PAD_CELLS (GS * GS + GS + 1)   // +1 plane/row/cell for unclamped +1 corners

// fp16 scratch, zero-initialized (pad region must read as 0.0)
__device__ __align__(128) __half g_trans[(size_t)NCH * (NSPATIAL + PAD_CELLS)];

struct U8 { unsigned r0, r1, r2, r3, r4, r5, r6, r7; };

__device__ __forceinline__ U8 ldg256_evict_last(const void* p) {
    U8 v;
    asm volatile("ld.global.L2::evict_last.v8.u32 {%0,%1,%2,%3,%4,%5,%6,%7}, [%8];"
                 : "=r"(v.r0), "=r"(v.r1), "=r"(v.r2), "=r"(v.r3),
                   "=r"(v.r4), "=r"(v.r5), "=r"(v.r6), "=r"(v.r7)
                 : "l"(p));
    return v;
}

__device__ __forceinline__ void stg256_evict_last(void* p, unsigned long long a,
                                                  unsigned long long b,
                                                  unsigned long long c,
                                                  unsigned long long d) {
    asm volatile("st.global.L2::evict_last.v4.u64 [%0], {%1,%2,%3,%4};"
                 :: "l"(p), "l"(a), "l"(b), "l"(c), "l"(d) : "memory");
}

__device__ __forceinline__ unsigned long long pack_f32x2(float lo, float hi) {
    unsigned long long r;
    asm("mov.b64 %0, {%1, %2};" : "=l"(r) : "f"(lo), "f"(hi));
    return r;
}

__device__ __forceinline__ void unpack_f32x2(unsigned long long v, float& lo, float& hi) {
    asm("mov.b64 {%0, %1}, %2;" : "=f"(lo), "=f"(hi) : "l"(v));
}

// acc = v * w + acc, two fp32 lanes per instruction (FFMA2)
__device__ __forceinline__ void ffma2(unsigned long long& acc, unsigned long long v,
                                      unsigned long long w) {
    asm("fma.rn.f32x2 %0, %1, %2, %0;" : "+l"(acc) : "l"(v), "l"(w));
}

__device__ __forceinline__ void addf2(unsigned long long& a, unsigned long long b) {
    asm("add.rn.f32x2 %0, %1, %0;" : "+l"(a) : "l"(b));
}

__global__ void __launch_bounds__(256) transpose_kernel(const float* __restrict__ in) {
    int idx = blockIdx.x * blockDim.x + threadIdx.x;
    if (idx >= NSPATIAL) return;
    __half2 v[NCH / 2];
#pragma unroll
    for (int c = 0; c < NCH; c += 2) {
        float a = __ldcs(in + (size_t)c * NSPATIAL + idx);        // streaming reads
        float b = __ldcs(in + (size_t)(c + 1) * NSPATIAL + idx);
        v[c / 2] = __floats2half2_rn(a, b);
    }
    const unsigned long long* s = reinterpret_cast<const unsigned long long*>(v);
    stg256_evict_last(g_trans + (size_t)idx * NCH, s[0], s[1], s[2], s[3]);
}

__global__ void __launch_bounds__(256, 6) gather_kernel(const float* __restrict__ coords,
                                                        float* __restrict__ out,
                                                        int N) {
    int t    = blockIdx.x * blockDim.x + threadIdx.x;
    int n    = t >> 1;        // point index
    int lane = t & 1;         // x-corner this thread owns (x0 or x0+1)
    if (n >= N) return;

    float c0 = __ldcs(coords + 3 * n + 0);
    float c1 = __ldcs(coords + 3 * n + 1);
    float c2 = __ldcs(coords + 3 * n + 2);
    // map [-1,1] -> [0,127]; +1 corners may land in the zero pad with weight 0
    float f0 = fminf(fmaxf(fmaf(c0, 63.5f, 63.5f), 0.0f), 127.0f);
    float f1 = fminf(fmaxf(fmaf(c1, 63.5f, 63.5f), 0.0f), 127.0f);
    float f2 = fminf(fmaxf(fmaf(c2, 63.5f, 63.5f), 0.0f), 127.0f);

    float fl0 = floorf(f0), fl1 = floorf(f1), fl2 = floorf(f2);
    float r0 = f0 - fl0, r1 = f1 - fl1, r2 = f2 - fl2;

    int cell00 = (((int)fl0 * GS + (int)fl1) * GS + (int)fl2);

    float wxl = lane ? r2 : (1.0f - r2);          // this lane's x weight
    float wzy[4];
    wzy[0] = (1.0f - r0) * (1.0f - r1) * wxl;     // z0 y0
    wzy[1] = (1.0f - r0) * r1 * wxl;              // z0 y1
    wzy[2] = r0 * (1.0f - r1) * wxl;              // z1 y0
    wzy[3] = r0 * r1 * wxl;                       // z1 y1

    // lane's cell: x0 (+0) or x0+1 (+32 B)
    const char* base = reinterpret_cast<const char*>(g_trans)
                     + (size_t)cell00 * 32 + (unsigned)lane * 32;

    unsigned long long acc[8];   // 8 packed f32x2 = 16 channels
#pragma unroll
    for (int k = 0; k < 8; k++) acc[k] = 0ull;    // two packed 0.0f

#pragma unroll
    for (int k = 0; k < 4; k++) {
        unsigned long long w2 = pack_f32x2(wzy[k], wzy[k]);
        U8 raw = ldg256_evict_last(
            base + ((size_t)(k >> 1) * (GS * GS) + (size_t)(k & 1) * GS) * 32);
        const unsigned* r = &raw.r0;
#pragma unroll
        for (int j = 0; j < 8; j++) {
            float2 v = __half22float2(*reinterpret_cast<const __half2*>(&r[j]));
            ffma2(acc[j], pack_f32x2(v.x, v.y), w2);
        }
    }

    // combine x0/x1 partials. lane0 stores ch0-7, lane1 stores ch8-15;
    // each lane sends the half its partner stores, receives its own half.
    unsigned mask = __activemask();
#pragma unroll
    for (int j = 0; j < 4; j++) {
        unsigned long long send = lane ? acc[j] : acc[4 + j];
        unsigned long long keep = lane ? acc[4 + j] : acc[j];
        unsigned long long got  = __shfl_xor_sync(mask, send, 1);
        addf2(keep, got);
        acc[j] = keep;   // acc[0..3] now hold this lane's final 8 channels
    }

    int chbase = lane * 8;
    size_t nn = (size_t)n;
#pragma unroll
    for (int j = 0; j < 4; j++) {
        float lo, hi;
        unpack_f32x2(acc[j], lo, hi);
        __stcs(out + (size_t)(chbase + 2 * j + 0) * N + nn, lo);
        __stcs(out + (size_t)(chbase + 2 * j + 1) * N + nn, hi);
    }
}

extern "C" void kernel_launch(void* const* d_in, const int* in_sizes, int n_in,
                              void* d_out, int out_size) {
    const float* input  = (const float*)d_in[0];
    const float* coords = (const float*)d_in[1];
    float* out = (float*)d_out;
    int N = in_sizes[1] / 3;

    transpose_kernel<<<(NSPATIAL + 255) / 256, 256>>>(input);

    long long threads = 2LL * N;
    int blocks = (int)((threads + 255) / 256);
    gather_kernel<<<blocks, 256>>>(coords, out, N);
}